// round 10
// baseline (speedup 1.0000x reference)
#include <cuda_runtime.h>

// Grad3D: out = |dx| + |dy| + |dz| with central differences, zero-padded.
// x shape (4, 1, 192, 224, 192) fp32, contiguous.
// Barrier-free flat kernel, prefetch distance 3: each thread owns one (h, w4)
// quad and marches DCHUNK planes. pp/cc/nn/n2 register planes + plane d+3 in
// flight. up/dn/lf/rt are direct global loads of plane d (L1-resident, loaded
// 3 iterations earlier). Output uses streaming stores to preserve L2 for input.

#define Nn 4
#define Dd 192
#define Hh 224
#define Ww 192
#define HW (Hh * Ww)          // 43008
#define DHW (Dd * HW)         // 8257536

#define BH 8                  // H rows per block
#define DCHUNK 16             // D planes per block
#define QPERROW (Ww / 4)      // 48

__global__ void __launch_bounds__(BH * QPERROW)
grad3d_kernel(const float* __restrict__ x, float* __restrict__ out)
{
    const int q   = threadIdx.x;            // 0..47
    const int ry  = threadIdx.y;            // 0..7
    const int gh  = blockIdx.x * BH + ry;   // 0..223
    const int d0  = blockIdx.y * DCHUNK;    // 0..176
    const int n   = blockIdx.z;

    const bool hasUp = (gh > 0);
    const bool hasDn = (gh < Hh - 1);
    const bool hasLf = (q > 0);
    const bool hasRt = (q < QPERROW - 1);

    const float* __restrict__ p =
        x + (size_t)n * DHW + gh * Ww + q * 4 + d0 * HW;   // plane d0
    float* __restrict__ dst =
        out + (size_t)n * DHW + gh * Ww + q * 4 + d0 * HW;

    const float4 Z = make_float4(0.f, 0.f, 0.f, 0.f);

    // Register planes: p0=x[d-1], c=x[d], n1=x[d+1], n2=x[d+2]; t=x[d+3] in flight.
    float4 p0 = (d0 > 0) ? *reinterpret_cast<const float4*>(p - HW) : Z;
    float4 c  = *reinterpret_cast<const float4*>(p);
    float4 n1 = *reinterpret_cast<const float4*>(p + HW);       // d0+1 <= 177, valid
    float4 n2 = *reinterpret_cast<const float4*>(p + 2 * HW);   // d0+2 <= 178, valid

#pragma unroll 2
    for (int k = 0; k < DCHUNK; ++k) {
        const int d = d0 + k;

        // Prefetch plane d+3 (consumed as n1 three iterations later).
        float4 t = (d + 3 < Dd) ? *reinterpret_cast<const float4*>(p + 3 * HW) : Z;

        // Neighbor reads on plane d — L1 hits (plane d loaded 3 iters earlier).
        float4 up = hasUp ? *reinterpret_cast<const float4*>(p - Ww) : Z;
        float4 dn = hasDn ? *reinterpret_cast<const float4*>(p + Ww) : Z;
        float  lf = hasLf ? p[-1] : 0.0f;
        float  rt = hasRt ? p[4]  : 0.0f;

        float4 o;
        o.x = 0.5f * (fabsf(c.y - lf)  + fabsf(dn.x - up.x) + fabsf(n1.x - p0.x));
        o.y = 0.5f * (fabsf(c.z - c.x) + fabsf(dn.y - up.y) + fabsf(n1.y - p0.y));
        o.z = 0.5f * (fabsf(c.w - c.y) + fabsf(dn.z - up.z) + fabsf(n1.z - p0.z));
        o.w = 0.5f * (fabsf(rt  - c.z) + fabsf(dn.w - up.w) + fabsf(n1.w - p0.w));

        __stcs(reinterpret_cast<float4*>(dst), o);   // streaming: no L2 pollution

        p0 = c; c = n1; n1 = n2; n2 = t;
        p   += HW;
        dst += HW;
    }
}

extern "C" void kernel_launch(void* const* d_in, const int* in_sizes, int n_in,
                              void* d_out, int out_size)
{
    const float* x = (const float*)d_in[0];
    float* out = (float*)d_out;
    dim3 block(QPERROW, BH);                // 48 x 8 = 384 threads
    dim3 grid(Hh / BH, Dd / DCHUNK, Nn);    // 28 x 12 x 4 = 1344 blocks
    grad3d_kernel<<<grid, block>>>(x, out);
}

// round 13
// speedup vs baseline: 1.1677x; 1.1677x over previous
#include <cuda_runtime.h>

// Grad3D: out = |dx| + |dy| + |dz| with central differences, zero-padded.
// x shape (4, 1, 192, 224, 192) fp32, contiguous.
// Register D-march (R6 structure, proven best): each thread owns one (h, w4)
// quad, marches DCHUNK planes. z-derivative & center in registers; smem
// (2 plane buffers) serves lf/rt/up/dn. One barrier per plane.
// R11 change: DCHUNK 16 -> 24 (D-halo 12.5% -> 8.3%, grid 896 = 2 clean waves).

#define Nn 4
#define Dd 192
#define Hh 224
#define Ww 192
#define HW (Hh * Ww)          // 43008
#define DHW (Dd * HW)         // 8257536

#define BH 8                  // H output rows per block
#define DCHUNK 24             // D planes per block (192/24 = 8 chunks)
#define NROWS (BH + 2)        // incl. halo rows (10)
#define ROWSTRIDE 200         // floats/row (800B): [3]=zero(w=-1), [4..195]=data, [196]=zero(w=192)
#define QPERROW (Ww / 4)      // 48
#define THREADS (NROWS * QPERROW)  // 480

__global__ void __launch_bounds__(THREADS, 3)
grad3d_kernel(const float* __restrict__ x, float* __restrict__ out)
{
    __shared__ __align__(16) float sm[2][NROWS * ROWSTRIDE];

    const int tid  = threadIdx.x;
    const int r    = tid / QPERROW;       // 0..9 (r=0, r=9 are halo rows)
    const int q    = tid - r * QPERROW;   // 0..47
    const int h0   = blockIdx.x * BH;     // 0..216
    const int d0   = blockIdx.y * DCHUNK; // 0..168
    const int dend = d0 + DCHUNK;
    const int n    = blockIdx.z;
    const int gh   = h0 - 1 + r;
    const bool inH  = (gh >= 0) && (gh < Hh);
    const bool comp = (r >= 1) && (r <= BH);

    // Zero guard columns (w=-1 at [3], w=W at [196]) in both buffers.
    if (q == 0) {
        sm[0][r * ROWSTRIDE + 3] = 0.0f;
        sm[0][r * ROWSTRIDE + 4 + Ww] = 0.0f;
        sm[1][r * ROWSTRIDE + 3] = 0.0f;
        sm[1][r * ROWSTRIDE + 4 + Ww] = 0.0f;
    }

    const float* __restrict__ src =
        x + (size_t)n * DHW + (size_t)(inH ? gh : 0) * Ww + q * 4;
    float* __restrict__ dst =
        out + (size_t)n * DHW + (size_t)(comp ? (gh) : 0) * Ww + q * 4;

    const int soff = r * ROWSTRIDE + 4 + q * 4;

    auto ldq = [&](int d) -> float4 {
        if (inH && (unsigned)d < (unsigned)Dd)
            return *reinterpret_cast<const float4*>(src + (size_t)d * HW);
        return make_float4(0.f, 0.f, 0.f, 0.f);
    };

    // Invariant entering iter d: regs r_prev=x[d-1], r_cur=x[d], r_next=x[d+1];
    // sm[d&1] holds plane d.
    float4 r_prev = ldq(d0 - 1);
    float4 r_cur  = ldq(d0);
    float4 r_next = ldq(d0 + 1);
    *reinterpret_cast<float4*>(&sm[d0 & 1][soff]) = r_cur;
    __syncthreads();

    for (int d = d0; d < dend; ++d) {
        // Prefetch plane d+2 (becomes r_next after rotation; last useful load is d+2==dend).
        float4 tmp = (d + 2 <= dend) ? ldq(d + 2)
                                     : make_float4(0.f, 0.f, 0.f, 0.f);

        // Publish plane d+1 for next iteration's neighbor reads.
        if (d + 1 < dend)
            *reinterpret_cast<float4*>(&sm[(d + 1) & 1][soff]) = r_next;

        if (comp) {
            const float* cb = &sm[d & 1][soff];
            float  lf = cb[-1];                                          // guard at q==0
            float  rt = cb[4];                                           // guard at q==47
            float4 up = *reinterpret_cast<const float4*>(cb - ROWSTRIDE);
            float4 dn = *reinterpret_cast<const float4*>(cb + ROWSTRIDE);

            float4 o;
            o.x = 0.5f * (fabsf(r_cur.y - lf)      + fabsf(dn.x - up.x) + fabsf(r_next.x - r_prev.x));
            o.y = 0.5f * (fabsf(r_cur.z - r_cur.x) + fabsf(dn.y - up.y) + fabsf(r_next.y - r_prev.y));
            o.z = 0.5f * (fabsf(r_cur.w - r_cur.y) + fabsf(dn.z - up.z) + fabsf(r_next.z - r_prev.z));
            o.w = 0.5f * (fabsf(rt     - r_cur.z)  + fabsf(dn.w - up.w) + fabsf(r_next.w - r_prev.w));

            *reinterpret_cast<float4*>(dst + (size_t)d * HW) = o;
        }

        __syncthreads();   // sm[(d+1)&1] published; reads of sm[d&1] complete
        r_prev = r_cur; r_cur = r_next; r_next = tmp;
    }
}

extern "C" void kernel_launch(void* const* d_in, const int* in_sizes, int n_in,
                              void* d_out, int out_size)
{
    const float* x = (const float*)d_in[0];
    float* out = (float*)d_out;
    dim3 grid(Hh / BH, Dd / DCHUNK, Nn);   // 28 x 8 x 4 = 896 blocks
    grad3d_kernel<<<grid, THREADS>>>(x, out);
}